// round 15
// baseline (speedup 1.0000x reference)
#include <cuda_runtime.h>
#include <cuda_fp16.h>
#include <cstdint>

// CARAFE: B=8, C=256, H=W=64, K=5, UP=2.
// out[b,c,2h+i,2w+j] = sum_{ki,kj} km[b,(i*2+j)*25+ki*5+kj,h,w] * x[b,c,h+ki-2,w+kj-2]
//
// R14 vs R13 (50.2us): SUBPIXEL-pairing instead of channel-pairing.
// Subpixels share the input tap, so:
//   acc01 += (w_u0[k], w_u1[k]) * (x_k, x_k)   [one HFMA2, NO broadcast instr]
// Weights packed (u0,u1)/(u2,u3) per tap: 50 half2 regs, zero PRMT in loop.
// x stored PRE-DUPLICATED (x,x) in smem at staging (pack_h2(v,v), free).
// Inner loop per channel: 25 LDS.32 + 50 HFMA2, nothing else.
// Precision identical to R12/R13: 3 chains (taps 0-8/9-16/17-24) in fp16,
// fp32 cross-chain combine -> rel_err ~5.6e-4.
// Schedule as R13: 592 CTAs single wave, 28/27 split, <=2 constant-bh
// segments, 2x64-thread groups w/ named barriers, NBUF=3, reg-prefetch+STS.

namespace {
constexpr int Hc = 64, Wc = 64;
constexpr int QQ = 100;
constexpr int THREADS = 128;
constexpr int CH4 = Hc * Wc / 4;          // 1024 float4 per channel image
constexpr int SROWH = 72;                 // half2 per staged row (4+64+4)
constexpr int CHPL  = 5 * SROWH;          // 360 half2 per channel-plane
constexpr int GBUFH = 4 * CHPL;           // 1440 half2 per buffer (4 channels)
constexpr int NBUF  = 3;
constexpr int NUNITS = 512 * 32;          // 16384
constexpr int NCTA = 592;                 // single wave
constexpr int NBIG = NUNITS - NCTA * 27;  // 400 CTAs take 28 units
constexpr int U4 = 8 * CH4;               // float4 stride of one unit (8 ch)
}

__device__ __forceinline__ uint32_t pack_dup(float v) {
    uint32_t r;   // (v,v) as half2
    asm("cvt.rn.f16x2.f32 %0, %1, %1;" : "=r"(r) : "f"(v));
    return r;
}
__device__ __forceinline__ __half2 pack_h2(float lo, float hi) {
    uint32_t r;   // cvt.rn.f16x2.f32 d, a, b : high<-a, low<-b
    asm("cvt.rn.f16x2.f32 %0, %1, %2;" : "=r"(r) : "f"(hi), "f"(lo));
    return *reinterpret_cast<__half2*>(&r);
}
__device__ __forceinline__ void group_bar(int id) {
    asm volatile("bar.sync %0, 64;" :: "r"(id) : "memory");
}

__global__ __launch_bounds__(THREADS, 4)
void carafe_kernel(const float* __restrict__ x,
                   const float* __restrict__ km,
                   float* __restrict__ out)
{
    const int tid = threadIdx.x;
    const int g   = tid >> 6;            // independent 64-thread group 0/1
    const int w   = tid & 63;            // pixel column / lane within group
    const int f   = w & 15;              // staged float4 column
    const int sch = w >> 4;              // channel (0..3) this thread stages

    // 2 groups x NBUF buffers x [ch 4][row 5][72] half2 (each entry = (x,x))
    __shared__ __align__(16) __half2 sbuf[2 * NBUF * GBUFH];
    __half2* sgrp = sbuf + g * (NBUF * GBUFH);

    // ---- static work range ----
    const int cta   = blockIdx.x;
    const int n     = (cta < NBIG) ? 28 : 27;
    const int start = (cta < NBIG) ? cta * 28 : 27 * cta + NBIG;

    // ---- zero halo cols (0..3, 68..71) of all buffers/channels/rows, once ----
    for (int e = w; e < NBUF * 4 * 5 * 8; e += 64) {
        int rc = e >> 3, cs = e & 7;
        int col = (cs < 4) ? cs : (64 + cs);
        sgrp[rc * SROWH + col] = __half2half2(__float2half(0.f));
    }

    const float4* x4 = (const float4*)x;
    const float4 zf4 = make_float4(0.f, 0.f, 0.f, 0.f);

    // dst half2 index for staged row r: (sch*5 + r)*SROWH + 4 + 4f
    const int dbase = (sch * 5) * SROWH + 4 + 4 * f;

    int u = start, rem = n;
    bool first = true;

    #pragma unroll 1
    while (rem > 0) {
        const int bh = u >> 5;
        const int g0 = u & 31;
        const int b  = bh >> 6;
        const int h  = bh & 63;
        int cnt = 32 - g0; if (cnt > rem) cnt = rem;

        if (!first) group_bar(g + 1);   // prev segment's readers done
        first = false;

        // ---- hoisted per-segment staging addressing (h fixed) ----
        bool rv[5]; int rb[5];
        #pragma unroll
        for (int r = 0; r < 5; r++) {
            int gr = h - 2 + r;
            rv[r] = (unsigned)gr < (unsigned)Hc;
            rb[r] = (rv[r] ? gr : 0) * 16 + f;
        }
        int base4 = ((b << 8) + (g0 << 3) + (g << 2) + sch) * CH4;  // += U4/unit

        // ---- prologue: prefetch unit 0 (this thread's channel, 5 rows) ----
        float4 pf[5];
        #pragma unroll
        for (int r = 0; r < 5; r++)
            pf[r] = rv[r] ? __ldg(x4 + base4 + rb[r]) : zf4;

        // ---- weights for this bh: (u0,u1)/(u2,u3) per tap, 50 half2 regs ----
        const float* kmp = km + ((size_t)b * QQ * Hc + h) * Wc + w;
        __half2 w01[25], w23[25];
        #pragma unroll
        for (int k = 0; k < 25; k++) {
            w01[k] = pack_h2(__ldg(kmp + (size_t)(k)      * (Hc * Wc)),
                             __ldg(kmp + (size_t)(25 + k) * (Hc * Wc)));
            w23[k] = pack_h2(__ldg(kmp + (size_t)(50 + k) * (Hc * Wc)),
                             __ldg(kmp + (size_t)(75 + k) * (Hc * Wc)));
        }

        float* optr = out + ((size_t)((b << 8) + (g0 << 3) + (g << 2)) * 128
                             + 2 * h) * 128 + 2 * w;
        int rdBuf = 0;

        #pragma unroll 1
        for (int j = 0; j < cnt; j++) {
            // ---- commit prefetched unit j: duplicate-pack fp16, STS.128 ----
            {
                __half2* dst = sgrp + rdBuf * GBUFH + dbase;
                #pragma unroll
                for (int r = 0; r < 5; r++) {
                    uint4 s;
                    s.x = pack_dup(pf[r].x); s.y = pack_dup(pf[r].y);
                    s.z = pack_dup(pf[r].z); s.w = pack_dup(pf[r].w);
                    *reinterpret_cast<uint4*>(dst + r * SROWH) = s;
                }
            }
            group_bar(g + 1);   // unit j visible; readers of j-3 long done

            // ---- prefetch unit j+1 (LDG latency hidden under compute) ----
            if (j + 1 < cnt) {
                base4 += U4;
                #pragma unroll
                for (int r = 0; r < 5; r++)
                    pf[r] = rv[r] ? __ldg(x4 + base4 + rb[r]) : zf4;
            }

            // ---- compute 4 channels: 25 LDS.32 + 50 HFMA2 each ----
            #pragma unroll
            for (int kch = 0; kch < 4; kch++) {
                const __half2* sp = sgrp + rdBuf * GBUFH + kch * CHPL + (w + 2);
                const __half2 z = __half2half2(__float2half(0.f));
                __half2 A01=z, A23=z;   // taps 0..8
                __half2 B01=z, B23=z;   // taps 9..16
                __half2 C01=z, C23=z;   // taps 17..24

                #pragma unroll
                for (int k = 0; k < 25; k++) {
                    __half2 xk = sp[(k / 5) * SROWH + (k % 5)];   // (x,x)
                    if (k < 9) {
                        A01 = __hfma2(w01[k], xk, A01);
                        A23 = __hfma2(w23[k], xk, A23);
                    } else if (k < 17) {
                        B01 = __hfma2(w01[k], xk, B01);
                        B23 = __hfma2(w23[k], xk, B23);
                    } else {
                        C01 = __hfma2(w01[k], xk, C01);
                        C23 = __hfma2(w23[k], xk, C23);
                    }
                }

                // epilogue: (A+B) fp16, cross-chain combine fp32
                float2 f01 = __half22float2(__hadd2(A01, B01));
                float2 c01 = __half22float2(C01);
                float2 f23 = __half22float2(__hadd2(A23, B23));
                float2 c23 = __half22float2(C23);

                // subpixel u=i*2+j -> (2h+i, 2w+j); lanes (u0,u1) row 2h,
                // lanes (u2,u3) row 2h+1
                float* o = optr + (size_t)kch * (128 * 128);
                *reinterpret_cast<float2*>(o)       = make_float2(f01.x + c01.x,
                                                                  f01.y + c01.y);
                *reinterpret_cast<float2*>(o + 128) = make_float2(f23.x + c23.x,
                                                                  f23.y + c23.y);
            }
            optr += (size_t)8 * (128 * 128);

            rdBuf++; if (rdBuf == NBUF) rdBuf = 0;
        }

        u += cnt; rem -= cnt;
    }
}

extern "C" void kernel_launch(void* const* d_in, const int* in_sizes, int n_in,
                              void* d_out, int out_size)
{
    const float* x  = (const float*)d_in[0];   // [8,256,64,64]
    const float* km = (const float*)d_in[1];   // [8,100,64,64]
    float* out = (float*)d_out;                // [8,256,128,128]

    carafe_kernel<<<NCTA, THREADS>>>(x, km, out);
}

// round 16
// speedup vs baseline: 1.0428x; 1.0428x over previous
#include <cuda_runtime.h>
#include <cuda_fp16.h>
#include <cstdint>

// CARAFE: B=8, C=256, H=W=64, K=5, UP=2.
// out[b,c,2h+i,2w+j] = sum_{ki,kj} km[b,(i*2+j)*25+ki*5+kj,h,w] * x[b,c,h+ki-2,w+kj-2]
//
// R15 vs R14 (67.0us FAILED) / R13 (50.2us best):
// Keep R14's subpixel-pairing (minimal instructions: weights packed
// (u0,u1)/(u2,u3), x pre-duplicated (x,x) in smem, 25 LDS + 50 HFMA2/channel)
// and fix R14's latency stalls:
//  - tap->chain ROUND-ROBIN (k%3): chains {0,3,..}/{1,4,..}/{2,5,..} (9/8/8)
//  - TWO channels computed together -> 12 independent chains, 4 HFMA2/tap,
//    same-chain reuse distance 12 instrs >> HFMA2 lat 4
//  - explicit distance-2 LDS prefetch in the fully-unrolled tap loop
// Precision structure unchanged in magnitude: fp16 chains + fp16 (c0+c1) add
// + fp32 cross-chain combine -> rel_err ~5e-4.
// Schedule as R13/R14: 592 CTAs single wave, 28/27 split, <=2 constant-bh
// segments, 2x64-thread groups, named barriers, NBUF=3, reg-prefetch + STS.

namespace {
constexpr int Hc = 64, Wc = 64;
constexpr int QQ = 100;
constexpr int THREADS = 128;
constexpr int CH4 = Hc * Wc / 4;          // 1024 float4 per channel image
constexpr int SROWH = 72;                 // half2 per staged row (4+64+4)
constexpr int CHPL  = 5 * SROWH;          // 360 half2 per channel-plane
constexpr int GBUFH = 4 * CHPL;           // 1440 half2 per buffer (4 channels)
constexpr int NBUF  = 3;
constexpr int NUNITS = 512 * 32;          // 16384
constexpr int NCTA = 592;                 // single wave
constexpr int NBIG = NUNITS - NCTA * 27;  // 400 CTAs take 28 units
constexpr int U4 = 8 * CH4;               // float4 stride of one unit (8 ch)
}

__device__ __forceinline__ uint32_t pack_dup(float v) {
    uint32_t r;   // (v,v) as half2
    asm("cvt.rn.f16x2.f32 %0, %1, %1;" : "=r"(r) : "f"(v));
    return r;
}
__device__ __forceinline__ __half2 pack_h2(float lo, float hi) {
    uint32_t r;   // cvt.rn.f16x2.f32 d, a, b : high<-a, low<-b
    asm("cvt.rn.f16x2.f32 %0, %1, %2;" : "=r"(r) : "f"(hi), "f"(lo));
    return *reinterpret_cast<__half2*>(&r);
}
__device__ __forceinline__ void group_bar(int id) {
    asm volatile("bar.sync %0, 64;" :: "r"(id) : "memory");
}

__global__ __launch_bounds__(THREADS, 4)
void carafe_kernel(const float* __restrict__ x,
                   const float* __restrict__ km,
                   float* __restrict__ out)
{
    const int tid = threadIdx.x;
    const int g   = tid >> 6;            // independent 64-thread group 0/1
    const int w   = tid & 63;            // pixel column / lane within group
    const int f   = w & 15;              // staged float4 column
    const int sch = w >> 4;              // channel (0..3) this thread stages

    // 2 groups x NBUF buffers x [ch 4][row 5][72] half2 (each entry = (x,x))
    __shared__ __align__(16) __half2 sbuf[2 * NBUF * GBUFH];
    __half2* sgrp = sbuf + g * (NBUF * GBUFH);

    // ---- static work range ----
    const int cta   = blockIdx.x;
    const int n     = (cta < NBIG) ? 28 : 27;
    const int start = (cta < NBIG) ? cta * 28 : 27 * cta + NBIG;

    // ---- zero halo cols (0..3, 68..71) of all buffers/channels/rows, once ----
    for (int e = w; e < NBUF * 4 * 5 * 8; e += 64) {
        int rc = e >> 3, cs = e & 7;
        int col = (cs < 4) ? cs : (64 + cs);
        sgrp[rc * SROWH + col] = __half2half2(__float2half(0.f));
    }

    const float4* x4 = (const float4*)x;
    const float4 zf4 = make_float4(0.f, 0.f, 0.f, 0.f);

    // dst half2 index for staged row r: (sch*5 + r)*SROWH + 4 + 4f
    const int dbase = (sch * 5) * SROWH + 4 + 4 * f;

    int u = start, rem = n;
    bool first = true;

    #pragma unroll 1
    while (rem > 0) {
        const int bh = u >> 5;
        const int g0 = u & 31;
        const int b  = bh >> 6;
        const int h  = bh & 63;
        int cnt = 32 - g0; if (cnt > rem) cnt = rem;

        if (!first) group_bar(g + 1);   // prev segment's readers done
        first = false;

        // ---- hoisted per-segment staging addressing (h fixed) ----
        bool rv[5]; int rb[5];
        #pragma unroll
        for (int r = 0; r < 5; r++) {
            int gr = h - 2 + r;
            rv[r] = (unsigned)gr < (unsigned)Hc;
            rb[r] = (rv[r] ? gr : 0) * 16 + f;
        }
        int base4 = ((b << 8) + (g0 << 3) + (g << 2) + sch) * CH4;  // += U4/unit

        // ---- prologue: prefetch unit 0 (this thread's channel, 5 rows) ----
        float4 pf[5];
        #pragma unroll
        for (int r = 0; r < 5; r++)
            pf[r] = rv[r] ? __ldg(x4 + base4 + rb[r]) : zf4;

        // ---- weights for this bh: (u0,u1)/(u2,u3) per tap, 50 half2 regs ----
        const float* kmp = km + ((size_t)b * QQ * Hc + h) * Wc + w;
        __half2 w01[25], w23[25];
        #pragma unroll
        for (int k = 0; k < 25; k++) {
            w01[k] = pack_h2(__ldg(kmp + (size_t)(k)      * (Hc * Wc)),
                             __ldg(kmp + (size_t)(25 + k) * (Hc * Wc)));
            w23[k] = pack_h2(__ldg(kmp + (size_t)(50 + k) * (Hc * Wc)),
                             __ldg(kmp + (size_t)(75 + k) * (Hc * Wc)));
        }

        float* optr = out + ((size_t)((b << 8) + (g0 << 3) + (g << 2)) * 128
                             + 2 * h) * 128 + 2 * w;
        int rdBuf = 0;

        #pragma unroll 1
        for (int j = 0; j < cnt; j++) {
            // ---- commit prefetched unit j: duplicate-pack fp16, STS.128 ----
            {
                __half2* dst = sgrp + rdBuf * GBUFH + dbase;
                #pragma unroll
                for (int r = 0; r < 5; r++) {
                    uint4 s;
                    s.x = pack_dup(pf[r].x); s.y = pack_dup(pf[r].y);
                    s.z = pack_dup(pf[r].z); s.w = pack_dup(pf[r].w);
                    *reinterpret_cast<uint4*>(dst + r * SROWH) = s;
                }
            }
            group_bar(g + 1);   // unit j visible; readers of j-3 long done

            // ---- prefetch unit j+1 (LDG latency hidden under compute) ----
            if (j + 1 < cnt) {
                base4 += U4;
                #pragma unroll
                for (int r = 0; r < 5; r++)
                    pf[r] = rv[r] ? __ldg(x4 + base4 + rb[r]) : zf4;
            }

            // ---- compute 4 channels as 2 channel-DUOS:
            //      per tap 4 HFMA2 into 12 rotating chains, LDS prefetch d=2 ----
            #pragma unroll
            for (int pc = 0; pc < 2; pc++) {
                const __half2* spa = sgrp + rdBuf * GBUFH + (2 * pc) * CHPL + (w + 2);
                const __half2* spb = spa + CHPL;

                const __half2 z = __half2half2(__float2half(0.f));
                // channel a: subpix (u0,u1) chains, (u2,u3) chains; same for b
                __half2 a01[3] = {z, z, z}, a23[3] = {z, z, z};
                __half2 b01[3] = {z, z, z}, b23[3] = {z, z, z};

                #define XOFF(k) (((k) / 5) * SROWH + ((k) % 5))
                __half2 ca = spa[XOFF(0)], cb = spb[XOFF(0)];
                __half2 na = spa[XOFF(1)], nb = spb[XOFF(1)];

                #pragma unroll
                for (int k = 0; k < 25; k++) {
                    __half2 ua = ca, ub = cb;
                    ca = na; cb = nb;
                    if (k + 2 < 25) { na = spa[XOFF(k + 2)]; nb = spb[XOFF(k + 2)]; }
                    const int ch = k % 3;          // rotating chain
                    a01[ch] = __hfma2(w01[k], ua, a01[ch]);
                    a23[ch] = __hfma2(w23[k], ua, a23[ch]);
                    b01[ch] = __hfma2(w01[k], ub, b01[ch]);
                    b23[ch] = __hfma2(w23[k], ub, b23[ch]);
                }
                #undef XOFF

                // epilogue: (chain0+chain1) fp16, + chain2 in fp32
                float2 fa01 = __half22float2(__hadd2(a01[0], a01[1]));
                float2 ca01 = __half22float2(a01[2]);
                float2 fa23 = __half22float2(__hadd2(a23[0], a23[1]));
                float2 ca23 = __half22float2(a23[2]);
                float2 fb01 = __half22float2(__hadd2(b01[0], b01[1]));
                float2 cb01 = __half22float2(b01[2]);
                float2 fb23 = __half22float2(__hadd2(b23[0], b23[1]));
                float2 cb23 = __half22float2(b23[2]);

                // subpixel u=i*2+j -> (2h+i, 2w+j); channels 2pc, 2pc+1
                float* oA = optr + (size_t)(2 * pc) * (128 * 128);
                float* oB = oA + (128 * 128);
                *reinterpret_cast<float2*>(oA)       = make_float2(fa01.x + ca01.x,
                                                                   fa01.y + ca01.y);
                *reinterpret_cast<float2*>(oA + 128) = make_float2(fa23.x + ca23.x,
                                                                   fa23.y + ca23.y);
                *reinterpret_cast<float2*>(oB)       = make_float2(fb01.x + cb01.x,
                                                                   fb01.y + cb01.y);
                *reinterpret_cast<float2*>(oB + 128) = make_float2(fb23.x + cb23.x,
                                                                   fb23.y + cb23.y);
            }
            optr += (size_t)8 * (128 * 128);

            rdBuf++; if (rdBuf == NBUF) rdBuf = 0;
        }

        u += cnt; rem -= cnt;
    }
}

extern "C" void kernel_launch(void* const* d_in, const int* in_sizes, int n_in,
                              void* d_out, int out_size)
{
    const float* x  = (const float*)d_in[0];   // [8,256,64,64]
    const float* km = (const float*)d_in[1];   // [8,100,64,64]
    float* out = (float*)d_out;                // [8,256,128,128]

    carafe_kernel<<<NCTA, THREADS>>>(x, km, out);
}